// round 10
// baseline (speedup 1.0000x reference)
#include <cuda_runtime.h>
#include <cuda_bf16.h>
#include <cstdint>
#include <cstddef>

// Problem constants
#define NB    8
#define CT    1024
#define LL    1024
#define HEADS 16
#define BN_EPS 1e-5f

// ---------------------------------------------------------------------------
// Scratch (static device allocations). Referenced ONLY from device code.
// ---------------------------------------------------------------------------
__device__ __nv_bfloat16 g_kT[(size_t)NB * HEADS * LL * 32];  // 8 MB  [n][h][l][32d]
__device__ __nv_bfloat16 g_qT[(size_t)NB * HEADS * LL * 32];  // 8 MB  [n][h][l][32d]
__device__ __nv_bfloat16 g_vB[(size_t)NB * CT * LL];          // 16 MB [n][c][l] == per-head [d][k]
__device__ float         g_mid[(size_t)NB * CT * LL];         // 32 MB tokens + kqv

// ---------------------------------------------------------------------------
// mma.sync / ldmatrix / cp.async helpers (base PTX, sm_80+)
// ---------------------------------------------------------------------------
__device__ __forceinline__ uint32_t smem_u32(const void* p) {
    uint32_t a;
    asm("{ .reg .u64 t; cvta.to.shared.u64 t, %1; cvt.u32.u64 %0, t; }"
        : "=r"(a) : "l"(p));
    return a;
}

#define LDSM_X4(R, A)                                                        \
    asm volatile("ldmatrix.sync.aligned.m8n8.x4.shared.b16 {%0,%1,%2,%3}, [%4];" \
                 : "=r"((R)[0]), "=r"((R)[1]), "=r"((R)[2]), "=r"((R)[3])    \
                 : "r"(A))

#define MMA16816(C, A, B0, B1)                                               \
    asm volatile("mma.sync.aligned.m16n8k16.row.col.f32.bf16.bf16.f32 "      \
                 "{%0,%1,%2,%3}, {%4,%5,%6,%7}, {%8,%9}, {%0,%1,%2,%3};"     \
                 : "+f"((C)[0]), "+f"((C)[1]), "+f"((C)[2]), "+f"((C)[3])    \
                 : "r"((A)[0]), "r"((A)[1]), "r"((A)[2]), "r"((A)[3]),       \
                   "r"(B0), "r"(B1))

#define MMA_TF32(C, A, B0, B1)                                               \
    asm volatile("mma.sync.aligned.m16n8k8.row.col.f32.tf32.tf32.f32 "       \
                 "{%0,%1,%2,%3}, {%4,%5,%6,%7}, {%8,%9}, {%0,%1,%2,%3};"     \
                 : "+f"((C)[0]), "+f"((C)[1]), "+f"((C)[2]), "+f"((C)[3])    \
                 : "r"((A)[0]), "r"((A)[1]), "r"((A)[2]), "r"((A)[3]),       \
                   "r"(B0), "r"(B1))

#define CP_ASYNC16(smem, gptr)                                               \
    asm volatile("cp.async.cg.shared.global [%0], [%1], 16;"                 \
                 :: "r"(smem), "l"(gptr))
#define CP_COMMIT() asm volatile("cp.async.commit_group;" ::: "memory")
#define CP_WAIT(N)  asm volatile("cp.async.wait_group %0;" :: "n"(N) : "memory")

__device__ __forceinline__ uint32_t packbf2(float x, float y) {
    __nv_bfloat162 t = __floats2bfloat162_rn(x, y);
    return *(uint32_t*)&t;
}
__device__ __forceinline__ uint32_t f2tf(uint32_t bits) {
    uint32_t r;
    asm("cvt.rna.tf32.f32 %0, %1;" : "=r"(r) : "r"(bits));
    return r;
}
__device__ __forceinline__ float ex2f(float x) {
    float r;
    asm("ex2.approx.ftz.f32 %0, %1;" : "=f"(r) : "f"(x));
    return r;
}

// ---------------------------------------------------------------------------
// Merged K/Q/V conv + BN, bf16 mma.sync, cp.async double buffered.
// Grid y 0..7 -> K conv, 8..15 -> Q conv, 16..31 -> V conv.
// Block: 64 cout x 128 L, 256 thr (8 warps, wm 2 x wn 4); warp 32co x 32l.
// Smem (fp32): W stride 40 words, X stride 132 words; bf16 cvt at frag load.
// ---------------------------------------------------------------------------
#define KQV_WS  40
#define KQV_XS  132
#define KQV_WSZ (64 * KQV_WS)
#define KQV_XSZ (32 * KQV_XS)
#define KQV_SMEM ((2 * KQV_WSZ + 2 * KQV_XSZ) * 4)   // 54272 B

__global__ __launch_bounds__(256) void kqv_conv_kernel(
    const float* __restrict__ tokens,
    const float* __restrict__ kw, const float* __restrict__ kb,
    const float* __restrict__ kg, const float* __restrict__ kbe,
    const float* __restrict__ km, const float* __restrict__ kvv,
    const float* __restrict__ qw, const float* __restrict__ qb,
    const float* __restrict__ qg, const float* __restrict__ qbe,
    const float* __restrict__ qm, const float* __restrict__ qvv,
    const float* __restrict__ vw, const float* __restrict__ vb,
    const float* __restrict__ vg, const float* __restrict__ vbe,
    const float* __restrict__ vm, const float* __restrict__ vvv)
{
    extern __shared__ float sm_f[];
    float* Wsm = sm_f;
    float* Xsm = sm_f + 2 * KQV_WSZ;
    const uint32_t ws_addr = smem_u32(Wsm);
    const uint32_t xs_addr = smem_u32(Xsm);

    const int n  = blockIdx.z;
    const int y  = blockIdx.y;
    const int l0 = blockIdx.x * 128;

    const int conv = (y < 8) ? 0 : (y < 16) ? 1 : 2;
    const int ly   = (conv == 0) ? y : (conv == 1) ? (y - 8) : (y - 16);
    const int co0  = ly * 64;

    const float *w, *bias, *gamma, *beta, *mean, *var;
    int cout_per_g;
    if (conv == 0)      { w = kw; bias = kb; gamma = kg; beta = kbe; mean = km; var = kvv; cout_per_g = 64; }
    else if (conv == 1) { w = qw; bias = qb; gamma = qg; beta = qbe; mean = qm; var = qvv; cout_per_g = 64; }
    else                { w = vw; bias = vb; gamma = vg; beta = vbe; mean = vm; var = vvv; cout_per_g = 128; }

    const int g = co0 / cout_per_g;
    const float* xg = tokens + ((size_t)n * CT + (size_t)g * 128) * LL + l0;

    const int tid  = threadIdx.x;
    const int wrp  = tid >> 5;
    const int lane = tid & 31;
    const int grp  = lane >> 2;
    const int tg   = lane & 3;
    const int wm   = wrp >> 2;     // 0..1
    const int wn   = wrp & 3;      // 0..3

    float c[2][4][4];
#pragma unroll
    for (int mt = 0; mt < 2; mt++)
#pragma unroll
        for (int nt = 0; nt < 4; nt++)
#pragma unroll
            for (int j = 0; j < 4; j++) c[mt][nt][j] = 0.f;

    auto issue = [&](int ch, int buf) {
#pragma unroll
        for (int i = 0; i < 4; i++) {      // X: 32 x 128 = 1024 uint4
            int idx = tid + i * 256;
            int r = idx >> 5, c4 = idx & 31;
            uint32_t dst = xs_addr + (uint32_t)(buf * KQV_XSZ + r * KQV_XS + c4 * 4) * 4;
            CP_ASYNC16(dst, xg + (size_t)(ch * 32 + r) * LL + c4 * 4);
        }
#pragma unroll
        for (int i = 0; i < 2; i++) {      // W: 64 x 32 = 512 uint4
            int idx = tid + i * 256;
            int r = idx >> 3, k4 = idx & 7;
            uint32_t dst = ws_addr + (uint32_t)(buf * KQV_WSZ + r * KQV_WS + k4 * 4) * 4;
            CP_ASYNC16(dst, w + (size_t)(co0 + r) * 128 + ch * 32 + k4 * 4);
        }
        CP_COMMIT();
    };

    issue(0, 0);
    for (int ch = 0; ch < 4; ch++) {       // cin 128, chunks of 32
        if (ch + 1 < 4) { issue(ch + 1, (ch + 1) & 1); CP_WAIT(1); }
        else            { CP_WAIT(0); }
        __syncthreads();

        const float* Wb = Wsm + (ch & 1) * KQV_WSZ;
        const float* Xb = Xsm + (ch & 1) * KQV_XSZ;

#pragma unroll
        for (int ks = 0; ks < 2; ks++) {   // k16 steps
            uint32_t a[2][4];
#pragma unroll
            for (int mt = 0; mt < 2; mt++) {
                const float* Wr  = Wb + (wm * 32 + mt * 16 + grp) * KQV_WS + ks * 16;
                const float* Wr8 = Wr + 8 * KQV_WS;
                float2 p00 = *(const float2*)(Wr  + 2 * tg);
                float2 p01 = *(const float2*)(Wr  + 8 + 2 * tg);
                float2 p10 = *(const float2*)(Wr8 + 2 * tg);
                float2 p11 = *(const float2*)(Wr8 + 8 + 2 * tg);
                a[mt][0] = packbf2(p00.x, p00.y);
                a[mt][1] = packbf2(p10.x, p10.y);
                a[mt][2] = packbf2(p01.x, p01.y);
                a[mt][3] = packbf2(p11.x, p11.y);
            }
#pragma unroll
            for (int nt = 0; nt < 4; nt++) {
                int col = wn * 32 + nt * 8 + grp;
                const float* X0 = Xb + (ks * 16 + 2 * tg) * KQV_XS + col;
                const float* X8 = X0 + 8 * KQV_XS;
                uint32_t b0 = packbf2(X0[0], X0[KQV_XS]);
                uint32_t b1 = packbf2(X8[0], X8[KQV_XS]);
                MMA16816(c[0][nt], a[0], b0, b1);
                MMA16816(c[1][nt], a[1], b0, b1);
            }
        }
        __syncthreads();
    }

    // Epilogue: BN + conv-specific store
#pragma unroll
    for (int mt = 0; mt < 2; mt++) {
        int coA = co0 + wm * 32 + mt * 16 + grp;
        int coB = coA + 8;
        float invA = gamma[coA] * rsqrtf(var[coA] + BN_EPS);
        float shA  = bias[coA] * invA + beta[coA] - mean[coA] * invA;
        float invB = gamma[coB] * rsqrtf(var[coB] + BN_EPS);
        float shB  = bias[coB] * invB + beta[coB] - mean[coB] * invB;

#pragma unroll
        for (int nt = 0; nt < 4; nt++) {
            int col = l0 + wn * 32 + nt * 8 + tg * 2;
            float vA0 = c[mt][nt][0] * invA + shA;
            float vA1 = c[mt][nt][1] * invA + shA;
            float vB0 = c[mt][nt][2] * invB + shB;
            float vB1 = c[mt][nt][3] * invB + shB;

            if (conv == 2) {   // V: bf16 [n][co][l]
                size_t iA = ((size_t)n * CT + coA) * LL + col;
                size_t iB = ((size_t)n * CT + coB) * LL + col;
                *(uint32_t*)&g_vB[iA] = packbf2(vA0, vA1);
                *(uint32_t*)&g_vB[iB] = packbf2(vB0, vB1);
            } else {           // K/Q: bf16 transposed [n][h][l][32]
                __nv_bfloat16* dst = (conv == 0) ? g_kT : g_qT;
                int hA = coA >> 5, dA = coA & 31;
                int hB = coB >> 5, dB = coB & 31;
                size_t bA = (((size_t)n * HEADS + hA) * LL + col) * 32 + dA;
                size_t bB = (((size_t)n * HEADS + hB) * LL + col) * 32 + dB;
                dst[bA]      = __float2bfloat16(vA0);
                dst[bA + 32] = __float2bfloat16(vA1);
                dst[bB]      = __float2bfloat16(vB0);
                dst[bB + 32] = __float2bfloat16(vB1);
            }
        }
    }
}

// ---------------------------------------------------------------------------
// FF conv (groups=1) + BN + residual, tf32 mma.sync, cp.async double buffer.
// Block: 128 cout x 64 L, 256 thr (8 warps, wm 4 x wn 2); warp 32co x 32l.
// Smem 55.3 KB -> 4 blocks/SM (vs 3 before): grid 1024 -> 1.73 waves.
// ---------------------------------------------------------------------------
#define FF_WS  36
#define FF_XS  72
#define FF_WSZ (128 * FF_WS)
#define FF_XSZ (32 * FF_XS)
#define FF_SMEM ((2 * FF_WSZ + 2 * FF_XSZ) * 4)   // 55296 B

__global__ __launch_bounds__(256) void ff_conv_kernel(
    const float* __restrict__ w,
    const float* __restrict__ bias, const float* __restrict__ gamma,
    const float* __restrict__ beta, const float* __restrict__ mean,
    const float* __restrict__ var, float* __restrict__ out)
{
    extern __shared__ uint32_t sm_u[];
    uint32_t* Wsm = sm_u;
    uint32_t* Xsm = sm_u + 2 * FF_WSZ;
    const uint32_t ws_addr = smem_u32(Wsm);
    const uint32_t xs_addr = smem_u32(Xsm);

    const int n   = blockIdx.z;
    const int co0 = blockIdx.y * 128;
    const int l0  = blockIdx.x * 64;

    const float* xg = g_mid + (size_t)n * CT * LL + l0;

    const int tid  = threadIdx.x;
    const int wrp  = tid >> 5;
    const int lane = tid & 31;
    const int grp  = lane >> 2;
    const int tg   = lane & 3;
    const int wm   = wrp >> 1;     // 0..3
    const int wn   = wrp & 1;      // 0..1

    float c[2][4][4];
#pragma unroll
    for (int mt = 0; mt < 2; mt++)
#pragma unroll
        for (int nt = 0; nt < 4; nt++)
#pragma unroll
            for (int j = 0; j < 4; j++) c[mt][nt][j] = 0.f;

    auto issue = [&](int ch, int buf) {
#pragma unroll
        for (int i = 0; i < 2; i++) {      // X: 32 x 64 = 512 uint4
            int idx = tid + i * 256;
            int r = idx >> 4, c4 = idx & 15;
            uint32_t dst = xs_addr + (uint32_t)(buf * FF_XSZ + r * FF_XS + c4 * 4) * 4;
            CP_ASYNC16(dst, xg + (size_t)(ch * 32 + r) * LL + c4 * 4);
        }
#pragma unroll
        for (int i = 0; i < 4; i++) {      // W: 128 x 32 = 1024 uint4
            int idx = tid + i * 256;
            int r = idx >> 3, k4 = idx & 7;
            uint32_t dst = ws_addr + (uint32_t)(buf * FF_WSZ + r * FF_WS + k4 * 4) * 4;
            CP_ASYNC16(dst, w + (size_t)(co0 + r) * 1024 + ch * 32 + k4 * 4);
        }
        CP_COMMIT();
    };

    issue(0, 0);
    for (int ch = 0; ch < 32; ch++) {      // cin 1024, chunks of 32
        if (ch + 1 < 32) { issue(ch + 1, (ch + 1) & 1); CP_WAIT(1); }
        else             { CP_WAIT(0); }
        __syncthreads();

        const uint32_t* Wb = Wsm + (ch & 1) * FF_WSZ;
        const uint32_t* Xb = Xsm + (ch & 1) * FF_XSZ;

#pragma unroll
        for (int ks = 0; ks < 4; ks++) {
            uint32_t a[2][4], b[4][2];
#pragma unroll
            for (int mt = 0; mt < 2; mt++) {
                int r0 = (wm * 32 + mt * 16 + grp) * FF_WS + ks * 8 + tg;
                a[mt][0] = f2tf(Wb[r0]);
                a[mt][1] = f2tf(Wb[r0 + 8 * FF_WS]);
                a[mt][2] = f2tf(Wb[r0 + 4]);
                a[mt][3] = f2tf(Wb[r0 + 8 * FF_WS + 4]);
            }
#pragma unroll
            for (int nt = 0; nt < 4; nt++) {
                int xb = (ks * 8 + tg) * FF_XS + wn * 32 + nt * 8 + grp;
                b[nt][0] = f2tf(Xb[xb]);
                b[nt][1] = f2tf(Xb[xb + 4 * FF_XS]);
            }
#pragma unroll
            for (int mt = 0; mt < 2; mt++)
#pragma unroll
                for (int nt = 0; nt < 4; nt++)
                    MMA_TF32(c[mt][nt], a[mt], b[nt][0], b[nt][1]);
        }
        __syncthreads();
    }

    // Epilogue: BN + residual (g_mid) -> out
#pragma unroll
    for (int mt = 0; mt < 2; mt++) {
        int coA = co0 + wm * 32 + mt * 16 + grp;
        int coB = coA + 8;
        float invA = gamma[coA] * rsqrtf(var[coA] + BN_EPS);
        float shA  = bias[coA] * invA + beta[coA] - mean[coA] * invA;
        float invB = gamma[coB] * rsqrtf(var[coB] + BN_EPS);
        float shB  = bias[coB] * invB + beta[coB] - mean[coB] * invB;

#pragma unroll
        for (int nt = 0; nt < 4; nt++) {
            int col = l0 + wn * 32 + nt * 8 + tg * 2;
            size_t iA = ((size_t)n * CT + coA) * LL + col;
            size_t iB = ((size_t)n * CT + coB) * LL + col;
            float vA0 = c[mt][nt][0] * invA + shA + g_mid[iA];
            float vA1 = c[mt][nt][1] * invA + shA + g_mid[iA + 1];
            float vB0 = c[mt][nt][2] * invB + shB + g_mid[iB];
            float vB1 = c[mt][nt][3] * invB + shB + g_mid[iB + 1];
            *(float2*)&out[iA] = make_float2(vA0, vA1);
            *(float2*)&out[iB] = make_float2(vB0, vB1);
        }
    }
}

// ---------------------------------------------------------------------------
// Attention (unchanged from R9 — measured 96.6 us).
// 8 warps x 16 q-rows, cp.async double-buffered K/V, ex2.approx.
// ---------------------------------------------------------------------------
#define ASMQ    0
#define ASMK    10240
#define ASMK_SZ 10240
#define ASMV    (ASMK + 2 * ASMK_SZ)
#define ASMV_SZ 17408
#define SM_ATT_TOTAL (ASMV + 2 * ASMV_SZ)   // 65536 B

__global__ __launch_bounds__(256) void attn_mma_kernel(
    const float* __restrict__ tokens)
{
    extern __shared__ char att_sm[];
    const uint32_t sb = smem_u32(att_sm);

    const int tid  = threadIdx.x;
    const int w    = tid >> 5;
    const int lane = tid & 31;
    const int grp  = lane >> 2;
    const int tg   = lane & 3;
    const int q0   = blockIdx.x * 128;
    const int h    = blockIdx.y;
    const int n    = blockIdx.z;

    const int rowoff = (lane & 7) + ((lane >> 4) & 1) * 8;
    const int colsel = (lane >> 3) & 1;

    {
        int row = tid >> 1, half = tid & 1;
        const uint4* src = (const uint4*)(g_qT +
            (((size_t)n * HEADS + h) * LL + q0 + row) * 32 + half * 16);
        uint4* dst = (uint4*)(att_sm + ASMQ + row * 80 + half * 32);
        dst[0] = src[0];
        dst[1] = src[1];
    }

    auto issue = [&](int c, int buf) {
        {
            int row = tid >> 1, half = tid & 1;
            const char* kg = (const char*)(g_kT +
                (((size_t)n * HEADS + h) * LL + c * 128 + row) * 32 + half * 16);
            uint32_t kdst = sb + ASMK + buf * ASMK_SZ + row * 80 + half * 32;
            CP_ASYNC16(kdst, kg);
            CP_ASYNC16(kdst + 16, kg + 16);
        }
        {
            int row = tid >> 2, quar = tid & 3;
            const char* vg = (const char*)(g_vB +
                ((size_t)n * CT + h * 64 + row) * LL + c * 128 + quar * 32);
            uint32_t vdst = sb + ASMV + buf * ASMV_SZ + row * 272 + quar * 64;
#pragma unroll
            for (int u = 0; u < 4; u++)
                CP_ASYNC16(vdst + u * 16, vg + u * 16);
        }
        CP_COMMIT();
    };

    issue(0, 0);
    __syncthreads();

    uint32_t qa[2][4];
    {
        int r = lane & 15, cb = (lane >> 4) * 16;
#pragma unroll
        for (int ks = 0; ks < 2; ks++) {
            uint32_t addr = sb + ASMQ + (uint32_t)((w * 16 + r) * 80 + ks * 32 + cb);
            LDSM_X4(qa[ks], addr);
        }
    }

    const float SC2 = 1.4426950408889634f / 32.0f;
    float o[8][4];
#pragma unroll
    for (int i = 0; i < 8; i++)
#pragma unroll
        for (int j = 0; j < 4; j++) o[i][j] = 0.f;
    float rs0 = 0.f, rs1 = 0.f;

    for (int c = 0; c < 8; c++) {
        if (c + 1 < 8) { issue(c + 1, (c + 1) & 1); CP_WAIT(1); }
        else           { CP_WAIT(0); }
        __syncthreads();

        const uint32_t kb = sb + ASMK + (c & 1) * ASMK_SZ;
        const uint32_t vb = sb + ASMV + (c & 1) * ASMV_SZ;

        float s[16][4];
#pragma unroll
        for (int i = 0; i < 16; i++)
#pragma unroll
            for (int j = 0; j < 4; j++) s[i][j] = 0.f;

#pragma unroll
        for (int np = 0; np < 8; np++) {
#pragma unroll
            for (int ks = 0; ks < 2; ks++) {
                uint32_t b[4];
                LDSM_X4(b, kb + (uint32_t)((np * 16 + rowoff) * 80
                                           + ks * 32 + colsel * 16));
                MMA16816(s[2 * np],     qa[ks], b[0], b[1]);
                MMA16816(s[2 * np + 1], qa[ks], b[2], b[3]);
            }
        }

#pragma unroll
        for (int kk = 0; kk < 8; kk++) {
            float e0a = ex2f(s[2 * kk][0] * SC2);
            float e0b = ex2f(s[2 * kk][1] * SC2);
            float e0c = ex2f(s[2 * kk][2] * SC2);
            float e0d = ex2f(s[2 * kk][3] * SC2);
            float e1a = ex2f(s[2 * kk + 1][0] * SC2);
            float e1b = ex2f(s[2 * kk + 1][1] * SC2);
            float e1c = ex2f(s[2 * kk + 1][2] * SC2);
            float e1d = ex2f(s[2 * kk + 1][3] * SC2);
            rs0 += e0a + e0b + e1a + e1b;
            rs1 += e0c + e0d + e1c + e1d;
            uint32_t a[4];
            a[0] = packbf2(e0a, e0b);
            a[1] = packbf2(e0c, e0d);
            a[2] = packbf2(e1a, e1b);
            a[3] = packbf2(e1c, e1d);

#pragma unroll
            for (int dp = 0; dp < 4; dp++) {
                uint32_t bv[4];
                LDSM_X4(bv, vb + (uint32_t)((dp * 16 + rowoff) * 272
                                            + kk * 32 + colsel * 16));
                MMA16816(o[2 * dp],     a, bv[0], bv[1]);
                MMA16816(o[2 * dp + 1], a, bv[2], bv[3]);
            }
        }
        __syncthreads();
    }

    rs0 += __shfl_xor_sync(0xFFFFFFFF, rs0, 1);
    rs0 += __shfl_xor_sync(0xFFFFFFFF, rs0, 2);
    rs1 += __shfl_xor_sync(0xFFFFFFFF, rs1, 1);
    rs1 += __shfl_xor_sync(0xFFFFFFFF, rs1, 2);
    const float inv0 = 1.0f / rs0;
    const float inv1 = 1.0f / rs1;

    const int qg0 = q0 + w * 16 + grp;
#pragma unroll
    for (int dt = 0; dt < 8; dt++) {
        int d = dt * 8 + tg * 2;
        size_t i00 = ((size_t)n * CT + h * 64 + d) * LL + qg0;
        size_t i01 = i00 + LL;
        g_mid[i00]     = tokens[i00]     + o[dt][0] * inv0;
        g_mid[i01]     = tokens[i01]     + o[dt][1] * inv0;
        g_mid[i00 + 8] = tokens[i00 + 8] + o[dt][2] * inv1;
        g_mid[i01 + 8] = tokens[i01 + 8] + o[dt][3] * inv1;
    }
}

// ---------------------------------------------------------------------------
extern "C" void kernel_launch(void* const* d_in, const int* in_sizes, int n_in,
                              void* d_out, int out_size)
{
    (void)in_sizes; (void)n_in; (void)out_size;
    const float* tokens = (const float*)d_in[0];
    const float* kw = (const float*)d_in[1];
    const float* kb = (const float*)d_in[2];
    const float* kg = (const float*)d_in[3];
    const float* kbe = (const float*)d_in[4];
    const float* km = (const float*)d_in[5];
    const float* kvv = (const float*)d_in[6];
    const float* qw = (const float*)d_in[7];
    const float* qb = (const float*)d_in[8];
    const float* qg = (const float*)d_in[9];
    const float* qbe = (const float*)d_in[10];
    const float* qm = (const float*)d_in[11];
    const float* qvv = (const float*)d_in[12];
    const float* vw = (const float*)d_in[13];
    const float* vb = (const float*)d_in[14];
    const float* vg = (const float*)d_in[15];
    const float* vbe = (const float*)d_in[16];
    const float* vm = (const float*)d_in[17];
    const float* vvv = (const float*)d_in[18];
    const float* fw = (const float*)d_in[19];
    const float* fb = (const float*)d_in[20];
    const float* fg = (const float*)d_in[21];
    const float* fbe = (const float*)d_in[22];
    const float* fm = (const float*)d_in[23];
    const float* fvv = (const float*)d_in[24];

    cudaFuncSetAttribute(kqv_conv_kernel,
                         cudaFuncAttributeMaxDynamicSharedMemorySize, KQV_SMEM);
    cudaFuncSetAttribute(ff_conv_kernel,
                         cudaFuncAttributeMaxDynamicSharedMemorySize, FF_SMEM);
    cudaFuncSetAttribute(attn_mma_kernel,
                         cudaFuncAttributeMaxDynamicSharedMemorySize, SM_ATT_TOTAL);

    // Merged K/Q/V convs (bf16): one launch, grid y = 8(K)+8(Q)+16(V)
    kqv_conv_kernel<<<dim3(8, 32, 8), 256, KQV_SMEM>>>(
        tokens,
        kw, kb, kg, kbe, km, kvv,
        qw, qb, qg, qbe, qm, qvv,
        vw, vb, vg, vbe, vm, vvv);

    // Attention + residual -> g_mid
    attn_mma_kernel<<<dim3(8, HEADS, 8), 256, SM_ATT_TOTAL>>>(tokens);

    // FF conv (tf32) + residual: g_mid -> d_out
    ff_conv_kernel<<<dim3(16, 8, 8), 256, FF_SMEM>>>(
        fw, fb, fg, fbe, fm, fvv, (float*)d_out);
}

// round 11
// speedup vs baseline: 1.5508x; 1.5508x over previous
#include <cuda_runtime.h>
#include <cuda_bf16.h>
#include <cstdint>
#include <cstddef>

// Problem constants
#define NB    8
#define CT    1024
#define LL    1024
#define HEADS 16
#define BN_EPS 1e-5f

// ---------------------------------------------------------------------------
// Scratch (static device allocations). Referenced ONLY from device code.
// ---------------------------------------------------------------------------
__device__ __nv_bfloat16 g_kT[(size_t)NB * HEADS * LL * 32];  // 8 MB  [n][h][l][32d]
__device__ __nv_bfloat16 g_qT[(size_t)NB * HEADS * LL * 32];  // 8 MB  [n][h][l][32d]
__device__ __nv_bfloat16 g_vB[(size_t)NB * CT * LL];          // 16 MB [n][c][l] == per-head [d][k]
__device__ float         g_mid[(size_t)NB * CT * LL];         // 32 MB tokens + kqv

// ---------------------------------------------------------------------------
// mma.sync / ldmatrix / cp.async helpers (base PTX, sm_80+)
// ---------------------------------------------------------------------------
__device__ __forceinline__ uint32_t smem_u32(const void* p) {
    uint32_t a;
    asm("{ .reg .u64 t; cvta.to.shared.u64 t, %1; cvt.u32.u64 %0, t; }"
        : "=r"(a) : "l"(p));
    return a;
}

#define LDSM_X4(R, A)                                                        \
    asm volatile("ldmatrix.sync.aligned.m8n8.x4.shared.b16 {%0,%1,%2,%3}, [%4];" \
                 : "=r"((R)[0]), "=r"((R)[1]), "=r"((R)[2]), "=r"((R)[3])    \
                 : "r"(A))

#define MMA16816(C, A, B0, B1)                                               \
    asm volatile("mma.sync.aligned.m16n8k16.row.col.f32.bf16.bf16.f32 "      \
                 "{%0,%1,%2,%3}, {%4,%5,%6,%7}, {%8,%9}, {%0,%1,%2,%3};"     \
                 : "+f"((C)[0]), "+f"((C)[1]), "+f"((C)[2]), "+f"((C)[3])    \
                 : "r"((A)[0]), "r"((A)[1]), "r"((A)[2]), "r"((A)[3]),       \
                   "r"(B0), "r"(B1))

#define MMA_TF32(C, A, B0, B1)                                               \
    asm volatile("mma.sync.aligned.m16n8k8.row.col.f32.tf32.tf32.f32 "       \
                 "{%0,%1,%2,%3}, {%4,%5,%6,%7}, {%8,%9}, {%0,%1,%2,%3};"     \
                 : "+f"((C)[0]), "+f"((C)[1]), "+f"((C)[2]), "+f"((C)[3])    \
                 : "r"((A)[0]), "r"((A)[1]), "r"((A)[2]), "r"((A)[3]),       \
                   "r"(B0), "r"(B1))

#define CP_ASYNC16(smem, gptr)                                               \
    asm volatile("cp.async.cg.shared.global [%0], [%1], 16;"                 \
                 :: "r"(smem), "l"(gptr))
#define CP_COMMIT() asm volatile("cp.async.commit_group;" ::: "memory")
#define CP_WAIT(N)  asm volatile("cp.async.wait_group %0;" :: "n"(N) : "memory")

__device__ __forceinline__ uint32_t packbf2(float x, float y) {
    __nv_bfloat162 t = __floats2bfloat162_rn(x, y);
    return *(uint32_t*)&t;
}
__device__ __forceinline__ uint32_t f2tf(uint32_t bits) {
    uint32_t r;
    asm("cvt.rna.tf32.f32 %0, %1;" : "=r"(r) : "r"(bits));
    return r;
}
__device__ __forceinline__ float ex2f(float x) {
    float r;
    asm("ex2.approx.ftz.f32 %0, %1;" : "=f"(r) : "f"(x));
    return r;
}

// Conv smem geometry (CO_TILE=64, L=128) — R9-proven strides
#define CV_WS  36
#define CV_XS  136
#define CV_WSZ (64 * CV_WS)
#define CV_XSZ (32 * CV_XS)
#define CV_SMEM ((2 * CV_WSZ + 2 * CV_XSZ) * 4)   // 53248 B -> 4 blocks/SM

// conv output modes
#define OUT_KT  0
#define OUT_QT  1
#define OUT_VB  2

// ---------------------------------------------------------------------------
// Merged K/Q/V conv + BN: R9 tf32 mainloop, CO_TILE=64, one launch.
// Grid y: 0..7 K, 8..15 Q, 16..31 V. Block 64co x 128l, 256 thr (2x4 warps).
// ---------------------------------------------------------------------------
__global__ __launch_bounds__(256) void kqv_conv_kernel(
    const float* __restrict__ tokens,
    const float* __restrict__ kw, const float* __restrict__ kb,
    const float* __restrict__ kg, const float* __restrict__ kbe,
    const float* __restrict__ km, const float* __restrict__ kvv,
    const float* __restrict__ qw, const float* __restrict__ qb,
    const float* __restrict__ qg, const float* __restrict__ qbe,
    const float* __restrict__ qm, const float* __restrict__ qvv,
    const float* __restrict__ vw, const float* __restrict__ vb,
    const float* __restrict__ vg, const float* __restrict__ vbe,
    const float* __restrict__ vm, const float* __restrict__ vvv)
{
    extern __shared__ uint32_t sm_u[];
    uint32_t* Wsm = sm_u;
    uint32_t* Xsm = sm_u + 2 * CV_WSZ;
    const uint32_t ws_addr = smem_u32(Wsm);
    const uint32_t xs_addr = smem_u32(Xsm);

    const int n  = blockIdx.z;
    const int y  = blockIdx.y;
    const int l0 = blockIdx.x * 128;

    const int mode = (y < 8) ? OUT_KT : (y < 16) ? OUT_QT : OUT_VB;
    const int ly   = (mode == OUT_KT) ? y : (mode == OUT_QT) ? (y - 8) : (y - 16);
    const int co0  = ly * 64;

    const float *w, *bias, *gamma, *beta, *mean, *var;
    int cout_per_g;
    if (mode == OUT_KT)      { w = kw; bias = kb; gamma = kg; beta = kbe; mean = km; var = kvv; cout_per_g = 64; }
    else if (mode == OUT_QT) { w = qw; bias = qb; gamma = qg; beta = qbe; mean = qm; var = qvv; cout_per_g = 64; }
    else                     { w = vw; bias = vb; gamma = vg; beta = vbe; mean = vm; var = vvv; cout_per_g = 128; }

    const int g = co0 / cout_per_g;
    const float* xg = tokens + ((size_t)n * CT + (size_t)g * 128) * LL + l0;

    const int tid  = threadIdx.x;
    const int wrp  = tid >> 5;
    const int lane = tid & 31;
    const int grp  = lane >> 2;
    const int tg   = lane & 3;
    const int wm   = wrp >> 2;     // 0..1
    const int wn   = wrp & 3;      // 0..3

    float c[2][4][4];
#pragma unroll
    for (int mt = 0; mt < 2; mt++)
#pragma unroll
        for (int nt = 0; nt < 4; nt++)
#pragma unroll
            for (int j = 0; j < 4; j++) c[mt][nt][j] = 0.f;

    auto issue = [&](int ch, int buf) {
#pragma unroll
        for (int i = 0; i < 4; i++) {      // X: 32 x 128
            int idx = tid + i * 256;
            int r = idx >> 5, c4 = idx & 31;
            uint32_t dst = xs_addr + (uint32_t)(buf * CV_XSZ + r * CV_XS + c4 * 4) * 4;
            CP_ASYNC16(dst, xg + (size_t)(ch * 32 + r) * LL + c4 * 4);
        }
#pragma unroll
        for (int i = 0; i < 2; i++) {      // W: 64 x 32
            int idx = tid + i * 256;
            int r = idx >> 3, k4 = idx & 7;
            uint32_t dst = ws_addr + (uint32_t)(buf * CV_WSZ + r * CV_WS + k4 * 4) * 4;
            CP_ASYNC16(dst, w + (size_t)(co0 + r) * 128 + ch * 32 + k4 * 4);
        }
        CP_COMMIT();
    };

    issue(0, 0);
    for (int ch = 0; ch < 4; ch++) {       // cin 128
        if (ch + 1 < 4) { issue(ch + 1, (ch + 1) & 1); CP_WAIT(1); }
        else            { CP_WAIT(0); }
        __syncthreads();

        const uint32_t* Wb = Wsm + (ch & 1) * CV_WSZ;
        const uint32_t* Xb = Xsm + (ch & 1) * CV_XSZ;

#pragma unroll
        for (int ks = 0; ks < 4; ks++) {
            uint32_t a[2][4], b[4][2];
#pragma unroll
            for (int mt = 0; mt < 2; mt++) {
                int r0 = (wm * 32 + mt * 16 + grp) * CV_WS + ks * 8 + tg;
                a[mt][0] = f2tf(Wb[r0]);
                a[mt][1] = f2tf(Wb[r0 + 8 * CV_WS]);
                a[mt][2] = f2tf(Wb[r0 + 4]);
                a[mt][3] = f2tf(Wb[r0 + 8 * CV_WS + 4]);
            }
#pragma unroll
            for (int nt = 0; nt < 4; nt++) {
                int xb = (ks * 8 + tg) * CV_XS + wn * 32 + nt * 8 + grp;
                b[nt][0] = f2tf(Xb[xb]);
                b[nt][1] = f2tf(Xb[xb + 4 * CV_XS]);
            }
#pragma unroll
            for (int mt = 0; mt < 2; mt++)
#pragma unroll
                for (int nt = 0; nt < 4; nt++)
                    MMA_TF32(c[mt][nt], a[mt], b[nt][0], b[nt][1]);
        }
        __syncthreads();
    }

    // Epilogue: BN + mode-specific store
#pragma unroll
    for (int mt = 0; mt < 2; mt++) {
        int coA = co0 + wm * 32 + mt * 16 + grp;
        int coB = coA + 8;
        float invA = gamma[coA] * rsqrtf(var[coA] + BN_EPS);
        float shA  = bias[coA] * invA + beta[coA] - mean[coA] * invA;
        float invB = gamma[coB] * rsqrtf(var[coB] + BN_EPS);
        float shB  = bias[coB] * invB + beta[coB] - mean[coB] * invB;

#pragma unroll
        for (int nt = 0; nt < 4; nt++) {
            int col = l0 + wn * 32 + nt * 8 + tg * 2;
            float vA0 = c[mt][nt][0] * invA + shA;
            float vA1 = c[mt][nt][1] * invA + shA;
            float vB0 = c[mt][nt][2] * invB + shB;
            float vB1 = c[mt][nt][3] * invB + shB;

            if (mode == OUT_VB) {   // V: bf16 [n][co][l]
                size_t iA = ((size_t)n * CT + coA) * LL + col;
                size_t iB = ((size_t)n * CT + coB) * LL + col;
                *(uint32_t*)&g_vB[iA] = packbf2(vA0, vA1);
                *(uint32_t*)&g_vB[iB] = packbf2(vB0, vB1);
            } else {                // K/Q: bf16 transposed [n][h][l][32]
                __nv_bfloat16* dst = (mode == OUT_KT) ? g_kT : g_qT;
                int hA = coA >> 5, dA = coA & 31;
                int hB = coB >> 5, dB = coB & 31;
                size_t bA = (((size_t)n * HEADS + hA) * LL + col) * 32 + dA;
                size_t bB = (((size_t)n * HEADS + hB) * LL + col) * 32 + dB;
                dst[bA]      = __float2bfloat16(vA0);
                dst[bA + 32] = __float2bfloat16(vA1);
                dst[bB]      = __float2bfloat16(vB0);
                dst[bB + 32] = __float2bfloat16(vB1);
            }
        }
    }
}

// ---------------------------------------------------------------------------
// FF conv (groups=1) + BN + residual: R9 tf32 mainloop, CO_TILE=64, L=128.
// 1024 blocks at 4/SM = 1.73 waves (same W traffic as R9, better tail).
// ---------------------------------------------------------------------------
__global__ __launch_bounds__(256) void ff_conv_kernel(
    const float* __restrict__ w,
    const float* __restrict__ bias, const float* __restrict__ gamma,
    const float* __restrict__ beta, const float* __restrict__ mean,
    const float* __restrict__ var, float* __restrict__ out)
{
    extern __shared__ uint32_t sm_u[];
    uint32_t* Wsm = sm_u;
    uint32_t* Xsm = sm_u + 2 * CV_WSZ;
    const uint32_t ws_addr = smem_u32(Wsm);
    const uint32_t xs_addr = smem_u32(Xsm);

    const int n   = blockIdx.z;
    const int co0 = blockIdx.y * 64;
    const int l0  = blockIdx.x * 128;

    const float* xg = g_mid + (size_t)n * CT * LL + l0;

    const int tid  = threadIdx.x;
    const int wrp  = tid >> 5;
    const int lane = tid & 31;
    const int grp  = lane >> 2;
    const int tg   = lane & 3;
    const int wm   = wrp >> 2;     // 0..1
    const int wn   = wrp & 3;      // 0..3

    float c[2][4][4];
#pragma unroll
    for (int mt = 0; mt < 2; mt++)
#pragma unroll
        for (int nt = 0; nt < 4; nt++)
#pragma unroll
            for (int j = 0; j < 4; j++) c[mt][nt][j] = 0.f;

    auto issue = [&](int ch, int buf) {
#pragma unroll
        for (int i = 0; i < 4; i++) {
            int idx = tid + i * 256;
            int r = idx >> 5, c4 = idx & 31;
            uint32_t dst = xs_addr + (uint32_t)(buf * CV_XSZ + r * CV_XS + c4 * 4) * 4;
            CP_ASYNC16(dst, xg + (size_t)(ch * 32 + r) * LL + c4 * 4);
        }
#pragma unroll
        for (int i = 0; i < 2; i++) {
            int idx = tid + i * 256;
            int r = idx >> 3, k4 = idx & 7;
            uint32_t dst = ws_addr + (uint32_t)(buf * CV_WSZ + r * CV_WS + k4 * 4) * 4;
            CP_ASYNC16(dst, w + (size_t)(co0 + r) * 1024 + ch * 32 + k4 * 4);
        }
        CP_COMMIT();
    };

    issue(0, 0);
    for (int ch = 0; ch < 32; ch++) {      // cin 1024
        if (ch + 1 < 32) { issue(ch + 1, (ch + 1) & 1); CP_WAIT(1); }
        else             { CP_WAIT(0); }
        __syncthreads();

        const uint32_t* Wb = Wsm + (ch & 1) * CV_WSZ;
        const uint32_t* Xb = Xsm + (ch & 1) * CV_XSZ;

#pragma unroll
        for (int ks = 0; ks < 4; ks++) {
            uint32_t a[2][4], b[4][2];
#pragma unroll
            for (int mt = 0; mt < 2; mt++) {
                int r0 = (wm * 32 + mt * 16 + grp) * CV_WS + ks * 8 + tg;
                a[mt][0] = f2tf(Wb[r0]);
                a[mt][1] = f2tf(Wb[r0 + 8 * CV_WS]);
                a[mt][2] = f2tf(Wb[r0 + 4]);
                a[mt][3] = f2tf(Wb[r0 + 8 * CV_WS + 4]);
            }
#pragma unroll
            for (int nt = 0; nt < 4; nt++) {
                int xb = (ks * 8 + tg) * CV_XS + wn * 32 + nt * 8 + grp;
                b[nt][0] = f2tf(Xb[xb]);
                b[nt][1] = f2tf(Xb[xb + 4 * CV_XS]);
            }
#pragma unroll
            for (int mt = 0; mt < 2; mt++)
#pragma unroll
                for (int nt = 0; nt < 4; nt++)
                    MMA_TF32(c[mt][nt], a[mt], b[nt][0], b[nt][1]);
        }
        __syncthreads();
    }

    // Epilogue: BN + residual (g_mid) -> out
#pragma unroll
    for (int mt = 0; mt < 2; mt++) {
        int coA = co0 + wm * 32 + mt * 16 + grp;
        int coB = coA + 8;
        float invA = gamma[coA] * rsqrtf(var[coA] + BN_EPS);
        float shA  = bias[coA] * invA + beta[coA] - mean[coA] * invA;
        float invB = gamma[coB] * rsqrtf(var[coB] + BN_EPS);
        float shB  = bias[coB] * invB + beta[coB] - mean[coB] * invB;

#pragma unroll
        for (int nt = 0; nt < 4; nt++) {
            int col = l0 + wn * 32 + nt * 8 + tg * 2;
            size_t iA = ((size_t)n * CT + coA) * LL + col;
            size_t iB = ((size_t)n * CT + coB) * LL + col;
            float vA0 = c[mt][nt][0] * invA + shA + g_mid[iA];
            float vA1 = c[mt][nt][1] * invA + shA + g_mid[iA + 1];
            float vB0 = c[mt][nt][2] * invB + shB + g_mid[iB];
            float vB1 = c[mt][nt][3] * invB + shB + g_mid[iB + 1];
            *(float2*)&out[iA] = make_float2(vA0, vA1);
            *(float2*)&out[iB] = make_float2(vB0, vB1);
        }
    }
}

// ---------------------------------------------------------------------------
// Attention (unchanged from R9 — measured 96.6 us).
// 8 warps x 16 q-rows, cp.async double-buffered K/V, ex2.approx.
// ---------------------------------------------------------------------------
#define ASMQ    0
#define ASMK    10240
#define ASMK_SZ 10240
#define ASMV    (ASMK + 2 * ASMK_SZ)
#define ASMV_SZ 17408
#define SM_ATT_TOTAL (ASMV + 2 * ASMV_SZ)   // 65536 B

__global__ __launch_bounds__(256) void attn_mma_kernel(
    const float* __restrict__ tokens)
{
    extern __shared__ char att_sm[];
    const uint32_t sb = smem_u32(att_sm);

    const int tid  = threadIdx.x;
    const int w    = tid >> 5;
    const int lane = tid & 31;
    const int grp  = lane >> 2;
    const int tg   = lane & 3;
    const int q0   = blockIdx.x * 128;
    const int h    = blockIdx.y;
    const int n    = blockIdx.z;

    const int rowoff = (lane & 7) + ((lane >> 4) & 1) * 8;
    const int colsel = (lane >> 3) & 1;

    {
        int row = tid >> 1, half = tid & 1;
        const uint4* src = (const uint4*)(g_qT +
            (((size_t)n * HEADS + h) * LL + q0 + row) * 32 + half * 16);
        uint4* dst = (uint4*)(att_sm + ASMQ + row * 80 + half * 32);
        dst[0] = src[0];
        dst[1] = src[1];
    }

    auto issue = [&](int c, int buf) {
        {
            int row = tid >> 1, half = tid & 1;
            const char* kg = (const char*)(g_kT +
                (((size_t)n * HEADS + h) * LL + c * 128 + row) * 32 + half * 16);
            uint32_t kdst = sb + ASMK + buf * ASMK_SZ + row * 80 + half * 32;
            CP_ASYNC16(kdst, kg);
            CP_ASYNC16(kdst + 16, kg + 16);
        }
        {
            int row = tid >> 2, quar = tid & 3;
            const char* vg = (const char*)(g_vB +
                ((size_t)n * CT + h * 64 + row) * LL + c * 128 + quar * 32);
            uint32_t vdst = sb + ASMV + buf * ASMV_SZ + row * 272 + quar * 64;
#pragma unroll
            for (int u = 0; u < 4; u++)
                CP_ASYNC16(vdst + u * 16, vg + u * 16);
        }
        CP_COMMIT();
    };

    issue(0, 0);
    __syncthreads();

    uint32_t qa[2][4];
    {
        int r = lane & 15, cb = (lane >> 4) * 16;
#pragma unroll
        for (int ks = 0; ks < 2; ks++) {
            uint32_t addr = sb + ASMQ + (uint32_t)((w * 16 + r) * 80 + ks * 32 + cb);
            LDSM_X4(qa[ks], addr);
        }
    }

    const float SC2 = 1.4426950408889634f / 32.0f;
    float o[8][4];
#pragma unroll
    for (int i = 0; i < 8; i++)
#pragma unroll
        for (int j = 0; j < 4; j++) o[i][j] = 0.f;
    float rs0 = 0.f, rs1 = 0.f;

    for (int c = 0; c < 8; c++) {
        if (c + 1 < 8) { issue(c + 1, (c + 1) & 1); CP_WAIT(1); }
        else           { CP_WAIT(0); }
        __syncthreads();

        const uint32_t kb = sb + ASMK + (c & 1) * ASMK_SZ;
        const uint32_t vb = sb + ASMV + (c & 1) * ASMV_SZ;

        float s[16][4];
#pragma unroll
        for (int i = 0; i < 16; i++)
#pragma unroll
            for (int j = 0; j < 4; j++) s[i][j] = 0.f;

#pragma unroll
        for (int np = 0; np < 8; np++) {
#pragma unroll
            for (int ks = 0; ks < 2; ks++) {
                uint32_t b[4];
                LDSM_X4(b, kb + (uint32_t)((np * 16 + rowoff) * 80
                                           + ks * 32 + colsel * 16));
                MMA16816(s[2 * np],     qa[ks], b[0], b[1]);
                MMA16816(s[2 * np + 1], qa[ks], b[2], b[3]);
            }
        }

#pragma unroll
        for (int kk = 0; kk < 8; kk++) {
            float e0a = ex2f(s[2 * kk][0] * SC2);
            float e0b = ex2f(s[2 * kk][1] * SC2);
            float e0c = ex2f(s[2 * kk][2] * SC2);
            float e0d = ex2f(s[2 * kk][3] * SC2);
            float e1a = ex2f(s[2 * kk + 1][0] * SC2);
            float e1b = ex2f(s[2 * kk + 1][1] * SC2);
            float e1c = ex2f(s[2 * kk + 1][2] * SC2);
            float e1d = ex2f(s[2 * kk + 1][3] * SC2);
            rs0 += e0a + e0b + e1a + e1b;
            rs1 += e0c + e0d + e1c + e1d;
            uint32_t a[4];
            a[0] = packbf2(e0a, e0b);
            a[1] = packbf2(e0c, e0d);
            a[2] = packbf2(e1a, e1b);
            a[3] = packbf2(e1c, e1d);

#pragma unroll
            for (int dp = 0; dp < 4; dp++) {
                uint32_t bv[4];
                LDSM_X4(bv, vb + (uint32_t)((dp * 16 + rowoff) * 272
                                            + kk * 32 + colsel * 16));
                MMA16816(o[2 * dp],     a, bv[0], bv[1]);
                MMA16816(o[2 * dp + 1], a, bv[2], bv[3]);
            }
        }
        __syncthreads();
    }

    rs0 += __shfl_xor_sync(0xFFFFFFFF, rs0, 1);
    rs0 += __shfl_xor_sync(0xFFFFFFFF, rs0, 2);
    rs1 += __shfl_xor_sync(0xFFFFFFFF, rs1, 1);
    rs1 += __shfl_xor_sync(0xFFFFFFFF, rs1, 2);
    const float inv0 = 1.0f / rs0;
    const float inv1 = 1.0f / rs1;

    const int qg0 = q0 + w * 16 + grp;
#pragma unroll
    for (int dt = 0; dt < 8; dt++) {
        int d = dt * 8 + tg * 2;
        size_t i00 = ((size_t)n * CT + h * 64 + d) * LL + qg0;
        size_t i01 = i00 + LL;
        g_mid[i00]     = tokens[i00]     + o[dt][0] * inv0;
        g_mid[i01]     = tokens[i01]     + o[dt][1] * inv0;
        g_mid[i00 + 8] = tokens[i00 + 8] + o[dt][2] * inv1;
        g_mid[i01 + 8] = tokens[i01 + 8] + o[dt][3] * inv1;
    }
}

// ---------------------------------------------------------------------------
extern "C" void kernel_launch(void* const* d_in, const int* in_sizes, int n_in,
                              void* d_out, int out_size)
{
    (void)in_sizes; (void)n_in; (void)out_size;
    const float* tokens = (const float*)d_in[0];
    const float* kw = (const float*)d_in[1];
    const float* kb = (const float*)d_in[2];
    const float* kg = (const float*)d_in[3];
    const float* kbe = (const float*)d_in[4];
    const float* km = (const float*)d_in[5];
    const float* kvv = (const float*)d_in[6];
    const float* qw = (const float*)d_in[7];
    const float* qb = (const float*)d_in[8];
    const float* qg = (const float*)d_in[9];
    const float* qbe = (const float*)d_in[10];
    const float* qm = (const float*)d_in[11];
    const float* qvv = (const float*)d_in[12];
    const float* vw = (const float*)d_in[13];
    const float* vb = (const float*)d_in[14];
    const float* vg = (const float*)d_in[15];
    const float* vbe = (const float*)d_in[16];
    const float* vm = (const float*)d_in[17];
    const float* vvv = (const float*)d_in[18];
    const float* fw = (const float*)d_in[19];
    const float* fb = (const float*)d_in[20];
    const float* fg = (const float*)d_in[21];
    const float* fbe = (const float*)d_in[22];
    const float* fm = (const float*)d_in[23];
    const float* fvv = (const float*)d_in[24];

    cudaFuncSetAttribute(kqv_conv_kernel,
                         cudaFuncAttributeMaxDynamicSharedMemorySize, CV_SMEM);
    cudaFuncSetAttribute(ff_conv_kernel,
                         cudaFuncAttributeMaxDynamicSharedMemorySize, CV_SMEM);
    cudaFuncSetAttribute(attn_mma_kernel,
                         cudaFuncAttributeMaxDynamicSharedMemorySize, SM_ATT_TOTAL);

    // Merged K/Q/V convs (tf32): one launch, grid y = 8(K)+8(Q)+16(V)
    kqv_conv_kernel<<<dim3(8, 32, 8), 256, CV_SMEM>>>(
        tokens,
        kw, kb, kg, kbe, km, kvv,
        qw, qb, qg, qbe, qm, qvv,
        vw, vb, vg, vbe, vm, vvv);

    // Attention + residual -> g_mid
    attn_mma_kernel<<<dim3(8, HEADS, 8), 256, SM_ATT_TOTAL>>>(tokens);

    // FF conv (tf32) + residual: g_mid -> d_out
    ff_conv_kernel<<<dim3(8, 16, 8), 256, CV_SMEM>>>(
        fw, fb, fg, fbe, fm, fvv, (float*)d_out);
}

// round 12
// speedup vs baseline: 1.6808x; 1.0838x over previous
#include <cuda_runtime.h>
#include <cuda_bf16.h>
#include <cstdint>
#include <cstddef>

// Problem constants
#define NB    8
#define CT    1024
#define LL    1024
#define HEADS 16
#define BN_EPS 1e-5f

// ---------------------------------------------------------------------------
// Scratch (static device allocations). Referenced ONLY from device code.
// ---------------------------------------------------------------------------
__device__ __nv_bfloat16 g_kT[(size_t)NB * HEADS * LL * 32];  // 8 MB  [n][h][l][32d]
__device__ __nv_bfloat16 g_qT[(size_t)NB * HEADS * LL * 32];  // 8 MB  [n][h][l][32d]
__device__ __nv_bfloat16 g_vB[(size_t)NB * CT * LL];          // 16 MB [n][c][l] == per-head [d][k]
__device__ float         g_mid[(size_t)NB * CT * LL];         // 32 MB tokens + kqv

// ---------------------------------------------------------------------------
// mma.sync / ldmatrix / cp.async helpers (base PTX, sm_80+)
// ---------------------------------------------------------------------------
__device__ __forceinline__ uint32_t smem_u32(const void* p) {
    uint32_t a;
    asm("{ .reg .u64 t; cvta.to.shared.u64 t, %1; cvt.u32.u64 %0, t; }"
        : "=r"(a) : "l"(p));
    return a;
}

#define LDSM_X4(R, A)                                                        \
    asm volatile("ldmatrix.sync.aligned.m8n8.x4.shared.b16 {%0,%1,%2,%3}, [%4];" \
                 : "=r"((R)[0]), "=r"((R)[1]), "=r"((R)[2]), "=r"((R)[3])    \
                 : "r"(A))

#define MMA16816(C, A, B0, B1)                                               \
    asm volatile("mma.sync.aligned.m16n8k16.row.col.f32.bf16.bf16.f32 "      \
                 "{%0,%1,%2,%3}, {%4,%5,%6,%7}, {%8,%9}, {%0,%1,%2,%3};"     \
                 : "+f"((C)[0]), "+f"((C)[1]), "+f"((C)[2]), "+f"((C)[3])    \
                 : "r"((A)[0]), "r"((A)[1]), "r"((A)[2]), "r"((A)[3]),       \
                   "r"(B0), "r"(B1))

#define MMA_TF32(C, A, B0, B1)                                               \
    asm volatile("mma.sync.aligned.m16n8k8.row.col.f32.tf32.tf32.f32 "       \
                 "{%0,%1,%2,%3}, {%4,%5,%6,%7}, {%8,%9}, {%0,%1,%2,%3};"     \
                 : "+f"((C)[0]), "+f"((C)[1]), "+f"((C)[2]), "+f"((C)[3])    \
                 : "r"((A)[0]), "r"((A)[1]), "r"((A)[2]), "r"((A)[3]),       \
                   "r"(B0), "r"(B1))

#define CP_ASYNC16(smem, gptr)                                               \
    asm volatile("cp.async.cg.shared.global [%0], [%1], 16;"                 \
                 :: "r"(smem), "l"(gptr))
#define CP_COMMIT() asm volatile("cp.async.commit_group;" ::: "memory")
#define CP_WAIT(N)  asm volatile("cp.async.wait_group %0;" :: "n"(N) : "memory")

__device__ __forceinline__ uint32_t packbf2(float x, float y) {
    __nv_bfloat162 t = __floats2bfloat162_rn(x, y);
    return *(uint32_t*)&t;
}
__device__ __forceinline__ float ex2f(float x) {
    float r;
    asm("ex2.approx.ftz.f32 %0, %1;" : "=f"(r) : "f"(x));
    return r;
}

// Conv smem geometry (CO_TILE=64, L=128) — R9-proven strides
#define CV_WS  36
#define CV_XS  136
#define CV_WSZ (64 * CV_WS)
#define CV_XSZ (32 * CV_XS)
#define CV_SMEM ((2 * CV_WSZ + 2 * CV_XSZ) * 4)   // 53248 B -> 4 blocks/SM

// conv output modes
#define OUT_KT  0
#define OUT_QT  1
#define OUT_VB  2

// ---------------------------------------------------------------------------
// Merged K/Q/V conv + BN: tf32 mainloop (raw fp32 bits, HW truncation),
// CO_TILE=64, one launch. Grid y: 0..7 K, 8..15 Q, 16..31 V.
// ---------------------------------------------------------------------------
__global__ __launch_bounds__(256) void kqv_conv_kernel(
    const float* __restrict__ tokens,
    const float* __restrict__ kw, const float* __restrict__ kb,
    const float* __restrict__ kg, const float* __restrict__ kbe,
    const float* __restrict__ km, const float* __restrict__ kvv,
    const float* __restrict__ qw, const float* __restrict__ qb,
    const float* __restrict__ qg, const float* __restrict__ qbe,
    const float* __restrict__ qm, const float* __restrict__ qvv,
    const float* __restrict__ vw, const float* __restrict__ vb,
    const float* __restrict__ vg, const float* __restrict__ vbe,
    const float* __restrict__ vm, const float* __restrict__ vvv)
{
    extern __shared__ uint32_t sm_u[];
    uint32_t* Wsm = sm_u;
    uint32_t* Xsm = sm_u + 2 * CV_WSZ;
    const uint32_t ws_addr = smem_u32(Wsm);
    const uint32_t xs_addr = smem_u32(Xsm);

    const int n  = blockIdx.z;
    const int y  = blockIdx.y;
    const int l0 = blockIdx.x * 128;

    const int mode = (y < 8) ? OUT_KT : (y < 16) ? OUT_QT : OUT_VB;
    const int ly   = (mode == OUT_KT) ? y : (mode == OUT_QT) ? (y - 8) : (y - 16);
    const int co0  = ly * 64;

    const float *w, *bias, *gamma, *beta, *mean, *var;
    int cout_per_g;
    if (mode == OUT_KT)      { w = kw; bias = kb; gamma = kg; beta = kbe; mean = km; var = kvv; cout_per_g = 64; }
    else if (mode == OUT_QT) { w = qw; bias = qb; gamma = qg; beta = qbe; mean = qm; var = qvv; cout_per_g = 64; }
    else                     { w = vw; bias = vb; gamma = vg; beta = vbe; mean = vm; var = vvv; cout_per_g = 128; }

    const int g = co0 / cout_per_g;
    const float* xg = tokens + ((size_t)n * CT + (size_t)g * 128) * LL + l0;

    const int tid  = threadIdx.x;
    const int wrp  = tid >> 5;
    const int lane = tid & 31;
    const int grp  = lane >> 2;
    const int tg   = lane & 3;
    const int wm   = wrp >> 2;     // 0..1
    const int wn   = wrp & 3;      // 0..3

    float c[2][4][4];
#pragma unroll
    for (int mt = 0; mt < 2; mt++)
#pragma unroll
        for (int nt = 0; nt < 4; nt++)
#pragma unroll
            for (int j = 0; j < 4; j++) c[mt][nt][j] = 0.f;

    auto issue = [&](int ch, int buf) {
#pragma unroll
        for (int i = 0; i < 4; i++) {      // X: 32 x 128
            int idx = tid + i * 256;
            int r = idx >> 5, c4 = idx & 31;
            uint32_t dst = xs_addr + (uint32_t)(buf * CV_XSZ + r * CV_XS + c4 * 4) * 4;
            CP_ASYNC16(dst, xg + (size_t)(ch * 32 + r) * LL + c4 * 4);
        }
#pragma unroll
        for (int i = 0; i < 2; i++) {      // W: 64 x 32
            int idx = tid + i * 256;
            int r = idx >> 3, k4 = idx & 7;
            uint32_t dst = ws_addr + (uint32_t)(buf * CV_WSZ + r * CV_WS + k4 * 4) * 4;
            CP_ASYNC16(dst, w + (size_t)(co0 + r) * 128 + ch * 32 + k4 * 4);
        }
        CP_COMMIT();
    };

    issue(0, 0);
    for (int ch = 0; ch < 4; ch++) {       // cin 128
        if (ch + 1 < 4) { issue(ch + 1, (ch + 1) & 1); CP_WAIT(1); }
        else            { CP_WAIT(0); }
        __syncthreads();

        const uint32_t* Wb = Wsm + (ch & 1) * CV_WSZ;
        const uint32_t* Xb = Xsm + (ch & 1) * CV_XSZ;

#pragma unroll
        for (int ks = 0; ks < 4; ks++) {
            uint32_t a[2][4], b[4][2];
#pragma unroll
            for (int mt = 0; mt < 2; mt++) {
                int r0 = (wm * 32 + mt * 16 + grp) * CV_WS + ks * 8 + tg;
                a[mt][0] = Wb[r0];
                a[mt][1] = Wb[r0 + 8 * CV_WS];
                a[mt][2] = Wb[r0 + 4];
                a[mt][3] = Wb[r0 + 8 * CV_WS + 4];
            }
#pragma unroll
            for (int nt = 0; nt < 4; nt++) {
                int xb = (ks * 8 + tg) * CV_XS + wn * 32 + nt * 8 + grp;
                b[nt][0] = Xb[xb];
                b[nt][1] = Xb[xb + 4 * CV_XS];
            }
#pragma unroll
            for (int mt = 0; mt < 2; mt++)
#pragma unroll
                for (int nt = 0; nt < 4; nt++)
                    MMA_TF32(c[mt][nt], a[mt], b[nt][0], b[nt][1]);
        }
        __syncthreads();
    }

    // Epilogue: BN + mode-specific store
#pragma unroll
    for (int mt = 0; mt < 2; mt++) {
        int coA = co0 + wm * 32 + mt * 16 + grp;
        int coB = coA + 8;
        float invA = gamma[coA] * rsqrtf(var[coA] + BN_EPS);
        float shA  = bias[coA] * invA + beta[coA] - mean[coA] * invA;
        float invB = gamma[coB] * rsqrtf(var[coB] + BN_EPS);
        float shB  = bias[coB] * invB + beta[coB] - mean[coB] * invB;

#pragma unroll
        for (int nt = 0; nt < 4; nt++) {
            int col = l0 + wn * 32 + nt * 8 + tg * 2;
            float vA0 = c[mt][nt][0] * invA + shA;
            float vA1 = c[mt][nt][1] * invA + shA;
            float vB0 = c[mt][nt][2] * invB + shB;
            float vB1 = c[mt][nt][3] * invB + shB;

            if (mode == OUT_VB) {   // V: bf16 [n][co][l]
                size_t iA = ((size_t)n * CT + coA) * LL + col;
                size_t iB = ((size_t)n * CT + coB) * LL + col;
                *(uint32_t*)&g_vB[iA] = packbf2(vA0, vA1);
                *(uint32_t*)&g_vB[iB] = packbf2(vB0, vB1);
            } else {                // K/Q: bf16 transposed [n][h][l][32]
                __nv_bfloat16* dst = (mode == OUT_KT) ? g_kT : g_qT;
                int hA = coA >> 5, dA = coA & 31;
                int hB = coB >> 5, dB = coB & 31;
                size_t bA = (((size_t)n * HEADS + hA) * LL + col) * 32 + dA;
                size_t bB = (((size_t)n * HEADS + hB) * LL + col) * 32 + dB;
                dst[bA]      = __float2bfloat16(vA0);
                dst[bA + 32] = __float2bfloat16(vA1);
                dst[bB]      = __float2bfloat16(vB0);
                dst[bB + 32] = __float2bfloat16(vB1);
            }
        }
    }
}

// ---------------------------------------------------------------------------
// FF conv (groups=1) + BN + residual: tf32 mainloop (raw fp32 bits),
// CO_TILE=64, L=128. 1024 blocks at 4/SM.
// ---------------------------------------------------------------------------
__global__ __launch_bounds__(256) void ff_conv_kernel(
    const float* __restrict__ w,
    const float* __restrict__ bias, const float* __restrict__ gamma,
    const float* __restrict__ beta, const float* __restrict__ mean,
    const float* __restrict__ var, float* __restrict__ out)
{
    extern __shared__ uint32_t sm_u[];
    uint32_t* Wsm = sm_u;
    uint32_t* Xsm = sm_u + 2 * CV_WSZ;
    const uint32_t ws_addr = smem_u32(Wsm);
    const uint32_t xs_addr = smem_u32(Xsm);

    const int n   = blockIdx.z;
    const int co0 = blockIdx.y * 64;
    const int l0  = blockIdx.x * 128;

    const float* xg = g_mid + (size_t)n * CT * LL + l0;

    const int tid  = threadIdx.x;
    const int wrp  = tid >> 5;
    const int lane = tid & 31;
    const int grp  = lane >> 2;
    const int tg   = lane & 3;
    const int wm   = wrp >> 2;     // 0..1
    const int wn   = wrp & 3;      // 0..3

    float c[2][4][4];
#pragma unroll
    for (int mt = 0; mt < 2; mt++)
#pragma unroll
        for (int nt = 0; nt < 4; nt++)
#pragma unroll
            for (int j = 0; j < 4; j++) c[mt][nt][j] = 0.f;

    auto issue = [&](int ch, int buf) {
#pragma unroll
        for (int i = 0; i < 4; i++) {
            int idx = tid + i * 256;
            int r = idx >> 5, c4 = idx & 31;
            uint32_t dst = xs_addr + (uint32_t)(buf * CV_XSZ + r * CV_XS + c4 * 4) * 4;
            CP_ASYNC16(dst, xg + (size_t)(ch * 32 + r) * LL + c4 * 4);
        }
#pragma unroll
        for (int i = 0; i < 2; i++) {
            int idx = tid + i * 256;
            int r = idx >> 3, k4 = idx & 7;
            uint32_t dst = ws_addr + (uint32_t)(buf * CV_WSZ + r * CV_WS + k4 * 4) * 4;
            CP_ASYNC16(dst, w + (size_t)(co0 + r) * 1024 + ch * 32 + k4 * 4);
        }
        CP_COMMIT();
    };

    issue(0, 0);
    for (int ch = 0; ch < 32; ch++) {      // cin 1024
        if (ch + 1 < 32) { issue(ch + 1, (ch + 1) & 1); CP_WAIT(1); }
        else             { CP_WAIT(0); }
        __syncthreads();

        const uint32_t* Wb = Wsm + (ch & 1) * CV_WSZ;
        const uint32_t* Xb = Xsm + (ch & 1) * CV_XSZ;

#pragma unroll
        for (int ks = 0; ks < 4; ks++) {
            uint32_t a[2][4], b[4][2];
#pragma unroll
            for (int mt = 0; mt < 2; mt++) {
                int r0 = (wm * 32 + mt * 16 + grp) * CV_WS + ks * 8 + tg;
                a[mt][0] = Wb[r0];
                a[mt][1] = Wb[r0 + 8 * CV_WS];
                a[mt][2] = Wb[r0 + 4];
                a[mt][3] = Wb[r0 + 8 * CV_WS + 4];
            }
#pragma unroll
            for (int nt = 0; nt < 4; nt++) {
                int xb = (ks * 8 + tg) * CV_XS + wn * 32 + nt * 8 + grp;
                b[nt][0] = Xb[xb];
                b[nt][1] = Xb[xb + 4 * CV_XS];
            }
#pragma unroll
            for (int mt = 0; mt < 2; mt++)
#pragma unroll
                for (int nt = 0; nt < 4; nt++)
                    MMA_TF32(c[mt][nt], a[mt], b[nt][0], b[nt][1]);
        }
        __syncthreads();
    }

    // Epilogue: BN + residual (g_mid) -> out
#pragma unroll
    for (int mt = 0; mt < 2; mt++) {
        int coA = co0 + wm * 32 + mt * 16 + grp;
        int coB = coA + 8;
        float invA = gamma[coA] * rsqrtf(var[coA] + BN_EPS);
        float shA  = bias[coA] * invA + beta[coA] - mean[coA] * invA;
        float invB = gamma[coB] * rsqrtf(var[coB] + BN_EPS);
        float shB  = bias[coB] * invB + beta[coB] - mean[coB] * invB;

#pragma unroll
        for (int nt = 0; nt < 4; nt++) {
            int col = l0 + wn * 32 + nt * 8 + tg * 2;
            size_t iA = ((size_t)n * CT + coA) * LL + col;
            size_t iB = ((size_t)n * CT + coB) * LL + col;
            float vA0 = c[mt][nt][0] * invA + shA + g_mid[iA];
            float vA1 = c[mt][nt][1] * invA + shA + g_mid[iA + 1];
            float vB0 = c[mt][nt][2] * invB + shB + g_mid[iB];
            float vB1 = c[mt][nt][3] * invB + shB + g_mid[iB + 1];
            *(float2*)&out[iA] = make_float2(vA0, vA1);
            *(float2*)&out[iB] = make_float2(vB0, vB1);
        }
    }
}

// ---------------------------------------------------------------------------
// Attention (unchanged from R9 — measured 96.6 us).
// 8 warps x 16 q-rows, cp.async double-buffered K/V, ex2.approx.
// ---------------------------------------------------------------------------
#define ASMQ    0
#define ASMK    10240
#define ASMK_SZ 10240
#define ASMV    (ASMK + 2 * ASMK_SZ)
#define ASMV_SZ 17408
#define SM_ATT_TOTAL (ASMV + 2 * ASMV_SZ)   // 65536 B

__global__ __launch_bounds__(256) void attn_mma_kernel(
    const float* __restrict__ tokens)
{
    extern __shared__ char att_sm[];
    const uint32_t sb = smem_u32(att_sm);

    const int tid  = threadIdx.x;
    const int w    = tid >> 5;
    const int lane = tid & 31;
    const int grp  = lane >> 2;
    const int tg   = lane & 3;
    const int q0   = blockIdx.x * 128;
    const int h    = blockIdx.y;
    const int n    = blockIdx.z;

    const int rowoff = (lane & 7) + ((lane >> 4) & 1) * 8;
    const int colsel = (lane >> 3) & 1;

    {
        int row = tid >> 1, half = tid & 1;
        const uint4* src = (const uint4*)(g_qT +
            (((size_t)n * HEADS + h) * LL + q0 + row) * 32 + half * 16);
        uint4* dst = (uint4*)(att_sm + ASMQ + row * 80 + half * 32);
        dst[0] = src[0];
        dst[1] = src[1];
    }

    auto issue = [&](int c, int buf) {
        {
            int row = tid >> 1, half = tid & 1;
            const char* kg = (const char*)(g_kT +
                (((size_t)n * HEADS + h) * LL + c * 128 + row) * 32 + half * 16);
            uint32_t kdst = sb + ASMK + buf * ASMK_SZ + row * 80 + half * 32;
            CP_ASYNC16(kdst, kg);
            CP_ASYNC16(kdst + 16, kg + 16);
        }
        {
            int row = tid >> 2, quar = tid & 3;
            const char* vg = (const char*)(g_vB +
                ((size_t)n * CT + h * 64 + row) * LL + c * 128 + quar * 32);
            uint32_t vdst = sb + ASMV + buf * ASMV_SZ + row * 272 + quar * 64;
#pragma unroll
            for (int u = 0; u < 4; u++)
                CP_ASYNC16(vdst + u * 16, vg + u * 16);
        }
        CP_COMMIT();
    };

    issue(0, 0);
    __syncthreads();

    uint32_t qa[2][4];
    {
        int r = lane & 15, cb = (lane >> 4) * 16;
#pragma unroll
        for (int ks = 0; ks < 2; ks++) {
            uint32_t addr = sb + ASMQ + (uint32_t)((w * 16 + r) * 80 + ks * 32 + cb);
            LDSM_X4(qa[ks], addr);
        }
    }

    const float SC2 = 1.4426950408889634f / 32.0f;
    float o[8][4];
#pragma unroll
    for (int i = 0; i < 8; i++)
#pragma unroll
        for (int j = 0; j < 4; j++) o[i][j] = 0.f;
    float rs0 = 0.f, rs1 = 0.f;

    for (int c = 0; c < 8; c++) {
        if (c + 1 < 8) { issue(c + 1, (c + 1) & 1); CP_WAIT(1); }
        else           { CP_WAIT(0); }
        __syncthreads();

        const uint32_t kb = sb + ASMK + (c & 1) * ASMK_SZ;
        const uint32_t vb = sb + ASMV + (c & 1) * ASMV_SZ;

        float s[16][4];
#pragma unroll
        for (int i = 0; i < 16; i++)
#pragma unroll
            for (int j = 0; j < 4; j++) s[i][j] = 0.f;

#pragma unroll
        for (int np = 0; np < 8; np++) {
#pragma unroll
            for (int ks = 0; ks < 2; ks++) {
                uint32_t b[4];
                LDSM_X4(b, kb + (uint32_t)((np * 16 + rowoff) * 80
                                           + ks * 32 + colsel * 16));
                MMA16816(s[2 * np],     qa[ks], b[0], b[1]);
                MMA16816(s[2 * np + 1], qa[ks], b[2], b[3]);
            }
        }

#pragma unroll
        for (int kk = 0; kk < 8; kk++) {
            float e0a = ex2f(s[2 * kk][0] * SC2);
            float e0b = ex2f(s[2 * kk][1] * SC2);
            float e0c = ex2f(s[2 * kk][2] * SC2);
            float e0d = ex2f(s[2 * kk][3] * SC2);
            float e1a = ex2f(s[2 * kk + 1][0] * SC2);
            float e1b = ex2f(s[2 * kk + 1][1] * SC2);
            float e1c = ex2f(s[2 * kk + 1][2] * SC2);
            float e1d = ex2f(s[2 * kk + 1][3] * SC2);
            rs0 += e0a + e0b + e1a + e1b;
            rs1 += e0c + e0d + e1c + e1d;
            uint32_t a[4];
            a[0] = packbf2(e0a, e0b);
            a[1] = packbf2(e0c, e0d);
            a[2] = packbf2(e1a, e1b);
            a[3] = packbf2(e1c, e1d);

#pragma unroll
            for (int dp = 0; dp < 4; dp++) {
                uint32_t bv[4];
                LDSM_X4(bv, vb + (uint32_t)((dp * 16 + rowoff) * 272
                                            + kk * 32 + colsel * 16));
                MMA16816(o[2 * dp],     a, bv[0], bv[1]);
                MMA16816(o[2 * dp + 1], a, bv[2], bv[3]);
            }
        }
        __syncthreads();
    }

    rs0 += __shfl_xor_sync(0xFFFFFFFF, rs0, 1);
    rs0 += __shfl_xor_sync(0xFFFFFFFF, rs0, 2);
    rs1 += __shfl_xor_sync(0xFFFFFFFF, rs1, 1);
    rs1 += __shfl_xor_sync(0xFFFFFFFF, rs1, 2);
    const float inv0 = 1.0f / rs0;
    const float inv1 = 1.0f / rs1;

    const int qg0 = q0 + w * 16 + grp;
#pragma unroll
    for (int dt = 0; dt < 8; dt++) {
        int d = dt * 8 + tg * 2;
        size_t i00 = ((size_t)n * CT + h * 64 + d) * LL + qg0;
        size_t i01 = i00 + LL;
        g_mid[i00]     = tokens[i00]     + o[dt][0] * inv0;
        g_mid[i01]     = tokens[i01]     + o[dt][1] * inv0;
        g_mid[i00 + 8] = tokens[i00 + 8] + o[dt][2] * inv1;
        g_mid[i01 + 8] = tokens[i01 + 8] + o[dt][3] * inv1;
    }
}

// ---------------------------------------------------------------------------
extern "C" void kernel_launch(void* const* d_in, const int* in_sizes, int n_in,
                              void* d_out, int out_size)
{
    (void)in_sizes; (void)n_in; (void)out_size;
    const float* tokens = (const float*)d_in[0];
    const float* kw = (const float*)d_in[1];
    const float* kb = (const float*)d_in[2];
    const float* kg = (const float*)d_in[3];
    const float* kbe = (const float*)d_in[4];
    const float* km = (const float*)d_in[5];
    const float* kvv = (const float*)d_in[6];
    const float* qw = (const float*)d_in[7];
    const float* qb = (const float*)d_in[8];
    const float* qg = (const float*)d_in[9];
    const float* qbe = (const float*)d_in[10];
    const float* qm = (const float*)d_in[11];
    const float* qvv = (const float*)d_in[12];
    const float* vw = (const float*)d_in[13];
    const float* vb = (const float*)d_in[14];
    const float* vg = (const float*)d_in[15];
    const float* vbe = (const float*)d_in[16];
    const float* vm = (const float*)d_in[17];
    const float* vvv = (const float*)d_in[18];
    const float* fw = (const float*)d_in[19];
    const float* fb = (const float*)d_in[20];
    const float* fg = (const float*)d_in[21];
    const float* fbe = (const float*)d_in[22];
    const float* fm = (const float*)d_in[23];
    const float* fvv = (const float*)d_in[24];

    cudaFuncSetAttribute(kqv_conv_kernel,
                         cudaFuncAttributeMaxDynamicSharedMemorySize, CV_SMEM);
    cudaFuncSetAttribute(ff_conv_kernel,
                         cudaFuncAttributeMaxDynamicSharedMemorySize, CV_SMEM);
    cudaFuncSetAttribute(attn_mma_kernel,
                         cudaFuncAttributeMaxDynamicSharedMemorySize, SM_ATT_TOTAL);

    // Merged K/Q/V convs (tf32): one launch, grid y = 8(K)+8(Q)+16(V)
    kqv_conv_kernel<<<dim3(8, 32, 8), 256, CV_SMEM>>>(
        tokens,
        kw, kb, kg, kbe, km, kvv,
        qw, qb, qg, qbe, qm, qvv,
        vw, vb, vg, vbe, vm, vvv);

    // Attention + residual -> g_mid
    attn_mma_kernel<<<dim3(8, HEADS, 8), 256, SM_ATT_TOTAL>>>(tokens);

    // FF conv (tf32) + residual: g_mid -> d_out
    ff_conv_kernel<<<dim3(8, 16, 8), 256, CV_SMEM>>>(
        fw, fb, fg, fbe, fm, fvv, (float*)d_out);
}